// round 12
// baseline (speedup 1.0000x reference)
#include <cuda_runtime.h>
#include <cuda_fp16.h>
#include <cstdint>
#include <math.h>

#define B_SZ   4
#define LEN_Q  21760
#define LEN_IN 21760
#define NQ     (B_SZ * LEN_Q)     // 87040
#define DM     256

// Scratch (allocation-free rule: __device__ globals)
__device__ __half g_value[(size_t)NQ * DM];     // [B, 8, Lin, 32] fp16 (head-major)
__device__ float  g_offattn[(size_t)NQ * 384];  // [B*Lq, 256 off | 128 attn]
__device__ __half g_outcore[(size_t)NQ * DM];   // [B*Lq, 256] fp16
__device__ __half g_wt16[256*256 + 384*256 + 256*256]; // wt_val | wt_offattn | wt_out
__device__ float  g_bias_oa[384];               // b_off || b_attn

// ---------------------------------------------------------------------------
// helpers
// ---------------------------------------------------------------------------
__device__ __forceinline__ uint32_t smem_u32(const void* p) {
    uint32_t a;
    asm("{ .reg .u64 t; cvta.to.shared.u64 t, %1; cvt.u32.u64 %0, t; }"
        : "=r"(a) : "l"(p));
    return a;
}
__device__ __forceinline__ uint32_t h2_bits(__half2 h) {
    union { __half2 h; uint32_t u; } cvt;
    cvt.h = h;
    return cvt.u;
}
__device__ __forceinline__ void cp16(uint32_t dst, const void* src) {
    asm volatile("cp.async.ca.shared.global [%0], [%1], 16;"
                 :: "r"(dst), "l"(src) : "memory");
}
#define CP_COMMIT() asm volatile("cp.async.commit_group;" ::: "memory")
#define CP_WAIT(n)  asm volatile("cp.async.wait_group %0;" :: "n"(n) : "memory")

__device__ __forceinline__ void ldm4(uint32_t* r, uint32_t addr) {
    asm volatile("ldmatrix.sync.aligned.m8n8.x4.shared.b16 {%0,%1,%2,%3}, [%4];"
        : "=r"(r[0]), "=r"(r[1]), "=r"(r[2]), "=r"(r[3]) : "r"(addr));
}
__device__ __forceinline__ void mma_f16(float* c, const uint32_t* a, const uint32_t* b) {
    asm volatile(
        "mma.sync.aligned.m16n8k16.row.col.f32.f16.f16.f32 "
        "{%0,%1,%2,%3}, {%4,%5,%6,%7}, {%8,%9}, {%0,%1,%2,%3};"
        : "+f"(c[0]), "+f"(c[1]), "+f"(c[2]), "+f"(c[3])
        : "r"(a[0]), "r"(a[1]), "r"(a[2]), "r"(a[3]), "r"(b[0]), "r"(b[1]));
}
// swizzled offset within a [128 rows x 32 halves] tile
__device__ __forceinline__ uint32_t swz(int row, int kh) {
    return (uint32_t)(row * 64 + ((((kh >> 3) ^ ((row >> 1) & 3))) << 4) + (kh & 7) * 2);
}

// ---------------------------------------------------------------------------
// Fused weight transpose (fp32 -> fp16, [K,N] -> [N,K]) + bias pack.
// ---------------------------------------------------------------------------
__global__ void transpose_all(const float* __restrict__ Wv,
                              const float* __restrict__ Wo,
                              const float* __restrict__ Wa,
                              const float* __restrict__ Wu,
                              const float* __restrict__ b_off,
                              const float* __restrict__ b_attn,
                              __half* __restrict__ wt,
                              float* __restrict__ bias_oa)
{
    const int z = blockIdx.z;
    const int bx = blockIdx.x, by = blockIdx.y;
    const int tx = threadIdx.x, ty = threadIdx.y;
    const int tid = ty * 32 + tx;

    if (z == 1 && bx == 0 && by == 0) {
        if (tid < 256) bias_oa[tid] = b_off[tid];
        if (tid < 128) bias_oa[256 + tid] = b_attn[tid];
    }
    if (z != 1 && bx >= 8) return;
    if (z == 1 && bx >= 12) return;

    const int n0 = bx << 5, k0 = by << 5;
    const float* src;
    __half* dst;
    int N, ncol0;
    if (z == 0)        { src = Wv; dst = wt;                 N = 256; ncol0 = n0; }
    else if (z == 2)   { src = Wu; dst = wt + 65536 + 98304; N = 256; ncol0 = n0; }
    else if (n0 < 256) { src = Wo; dst = wt + 65536;         N = 256; ncol0 = n0; }
    else               { src = Wa; dst = wt + 65536;         N = 128; ncol0 = n0 - 256; }

    __shared__ float t[32][33];
    #pragma unroll
    for (int i = 0; i < 4; ++i)
        t[ty + 8 * i][tx] = src[(size_t)(k0 + ty + 8 * i) * N + ncol0 + tx];
    __syncthreads();
    #pragma unroll
    for (int i = 0; i < 4; ++i)
        dst[(size_t)(n0 + ty + 8 * i) * 256 + k0 + tx] = __float2half(t[tx][ty + 8 * i]);
}

// ---------------------------------------------------------------------------
// A-resident fp16 GEMM: C[128, ntiles*128] = A[128,256] @ Bt^T + bias
// A tile held in SMEM fp16 (64KB); read from DRAM once per CTA.
// A_HALF: A already fp16 -> cp.async directly; else LDG fp32 + cvt + STS.
// OMODE: 0 = fp32 row-major, 1 = fp16 row-major, 2 = fp16 head-major
//        ([B][8][LEN_IN][32], col -> head*32+ch; tiles never cross batches).
// ---------------------------------------------------------------------------
#define SMEM_A_BYTES 65536
#define B_STAGE 8192

template<bool A_HALF, int OMODE>
__global__ __launch_bounds__(256, 2)
void gemm_f16(const void* __restrict__ Av, const __half* __restrict__ Bt,
              const float* __restrict__ bias, void* __restrict__ Cv,
              int ldc, int ntiles)
{
    extern __shared__ char smc[];
    const uint32_t sb = smem_u32(smc);          // A region
    const uint32_t sB = sb + SMEM_A_BYTES;      // B stages
    const int tid = threadIdx.x, wid = tid >> 5, lane = tid & 31;
    const int bm = blockIdx.x << 7;
    const int wm = (wid >> 2) << 6;
    const int wn = (wid & 3) << 5;

    const int arow = tid >> 1, ahalf = tid & 1;

    auto cpB = [&](int g, uint32_t dst) {       // global chunk g = bn*8 + c
        const int bnp = g >> 3, cp = g & 7;
        #pragma unroll
        for (int j = 0; j < 2; ++j) {
            const int kh = ahalf * 16 + j * 8;
            cp16(dst + swz(arow, kh),
                 Bt + (size_t)(bnp * 128 + arow) * 256 + cp * 32 + kh);
        }
        CP_COMMIT();
    };

    const int G = ntiles * 8;

    if constexpr (A_HALF) {
        const __half* Agh = (const __half*)Av + (size_t)bm * 256;
        #pragma unroll
        for (int c = 0; c < 8; ++c)
            #pragma unroll
            for (int j = 0; j < 2; ++j) {
                const int kh = ahalf * 16 + j * 8;
                cp16(sb + c * B_STAGE + swz(arow, kh),
                     Agh + (size_t)arow * 256 + c * 32 + kh);
            }
        cpB(0, sB);                 // group0 = A(all) + B0
        cpB(1, sB + B_STAGE);       // group1 = B1
    } else {
        cpB(0, sB);
        cpB(1, sB + B_STAGE);
        const float* Ag = (const float*)Av + (size_t)bm * 256;
        #pragma unroll
        for (int c = 0; c < 8; ++c) {
            const float* p = Ag + (size_t)arow * 256 + c * 32 + ahalf * 16;
            #pragma unroll
            for (int j = 0; j < 4; ++j) {
                float4 v = *(const float4*)(p + j * 4);
                const int kh = ahalf * 16 + j * 4;
                uint32_t h01 = h2_bits(__floats2half2_rn(v.x, v.y));
                uint32_t h23 = h2_bits(__floats2half2_rn(v.z, v.w));
                asm volatile("st.shared.v2.b32 [%0], {%1, %2};"
                    :: "r"(sb + c * B_STAGE + swz(arow, kh)), "r"(h01), "r"(h23)
                    : "memory");
            }
        }
    }

    // per-warp ldmatrix lane offsets (within a 32-half chunk; ks=1 -> XOR 32)
    uint32_t aoff[4], boff[2];
    {
        const int ar = (lane & 15), akh = (lane >> 4) * 8;
        #pragma unroll
        for (int mt = 0; mt < 4; ++mt) aoff[mt] = swz(wm + mt * 16 + ar, akh);
        const int br0 = (lane & 7) + ((lane >> 4) << 3), bkh = lane & 8;
        #pragma unroll
        for (int n2 = 0; n2 < 2; ++n2) boff[n2] = swz(wn + n2 * 16 + br0, bkh);
    }
    const int gm = lane >> 2, gn2 = (lane & 3) * 2;
    const int bq = bm / LEN_IN;                  // batch (OMODE 2); tiles don't cross

    for (int bn = 0; bn < ntiles; ++bn) {
        float acc[4][4][4] = {};
        #pragma unroll
        for (int c = 0; c < 8; ++c) {
            const int g = bn * 8 + c;
            const uint32_t stA = sb + (uint32_t)c * B_STAGE;
            const uint32_t stB = sB + (uint32_t)(g & 1) * B_STAGE;
            if (g == G - 1) CP_WAIT(0); else CP_WAIT(1);
            __syncthreads();

            #pragma unroll
            for (int ks = 0; ks < 2; ++ks) {
                const uint32_t xo = ks * 32;
                uint32_t afr[4][4], bfr[2][4];
                #pragma unroll
                for (int mt = 0; mt < 4; ++mt) ldm4(afr[mt], stA + (aoff[mt] ^ xo));
                #pragma unroll
                for (int n2 = 0; n2 < 2; ++n2) ldm4(bfr[n2], stB + (boff[n2] ^ xo));
                #pragma unroll
                for (int mt = 0; mt < 4; ++mt)
                    #pragma unroll
                    for (int nt = 0; nt < 4; ++nt)
                        mma_f16(acc[mt][nt], afr[mt], &bfr[nt >> 1][(nt & 1) * 2]);
            }
            __syncthreads();
            if (g + 2 < G) cpB(g + 2, stB);
        }

        // epilogue for this N-tile
        #pragma unroll
        for (int nt = 0; nt < 4; ++nt) {
            const int col = bn * 128 + wn + nt * 8 + gn2;
            const float b0 = bias[col], b1 = bias[col + 1];
            #pragma unroll
            for (int mt = 0; mt < 4; ++mt) {
                const int r0 = bm + wm + mt * 16 + gm;
                if (OMODE == 2) {
                    __half* C = (__half*)Cv;
                    const int head = col >> 5, ch = col & 31;
                    const int lr = r0 - bq * LEN_IN;
                    const size_t base =
                        ((size_t)(bq * 8 + head) * LEN_IN + lr) * 32 + ch;
                    *(__half2*)(C + base) =
                        __floats2half2_rn(acc[mt][nt][0] + b0, acc[mt][nt][1] + b1);
                    *(__half2*)(C + base + 8 * 32) =
                        __floats2half2_rn(acc[mt][nt][2] + b0, acc[mt][nt][3] + b1);
                } else if (OMODE == 1) {
                    __half* C = (__half*)Cv;
                    *(__half2*)(C + (size_t)r0 * ldc + col) =
                        __floats2half2_rn(acc[mt][nt][0] + b0, acc[mt][nt][1] + b1);
                    *(__half2*)(C + (size_t)(r0 + 8) * ldc + col) =
                        __floats2half2_rn(acc[mt][nt][2] + b0, acc[mt][nt][3] + b1);
                } else {
                    float* C = (float*)Cv;
                    float2 o0 = { acc[mt][nt][0] + b0, acc[mt][nt][1] + b1 };
                    float2 o1 = { acc[mt][nt][2] + b0, acc[mt][nt][3] + b1 };
                    *(float2*)(C + (size_t)r0 * ldc + col) = o0;
                    *(float2*)(C + (size_t)(r0 + 8) * ldc + col) = o1;
                }
            }
        }
    }
}

// ---------------------------------------------------------------------------
// Deformable sampling v5: 256 threads = 1 query, warp = 1 head.
// value is head-major [B][8][Lin][32] so an x-adjacent corner pair is 128B
// contiguous. Lane = (row r = lane>>4, xside = (lane>>3)&1, 4-ch group
// g = lane&7). ONE LDG.64 per (sample) covers all 4 corners of the head.
// Setup folds clamping+validity into per-axis pair weights on pixels
// (p, p+1) x (q, q+1); records {byteoff, weight} per (row,xside) in smem.
// Final: 8 shfl+add reduce over (row, xside); fp16 store.
// ---------------------------------------------------------------------------
__global__ __launch_bounds__(256)
void msda_sample5(const __half* __restrict__ value,   // [B, 8, Lin, 32] fp16
                  const float* __restrict__ offattn,  // [B*Lq, 384]
                  const float* __restrict__ refpts,   // [B, Lq, 4, 2]
                  const int*   __restrict__ spatial,  // [4, 2]
                  const int*   __restrict__ lstart,   // [4]
                  __half* __restrict__ outcore)       // [B*Lq, 256] fp16
{
    const int qg  = blockIdx.x;
    const int b   = qg / LEN_Q;
    const int tid = threadIdx.x, head = tid >> 5, lane = tid & 31;

    __shared__ float s_ref[8];
    __shared__ int   s_H[4], s_W[4], s_S[4];
    __shared__ __align__(16) float s_par[8][16][8];  // [head][s][{off,w} x4]

    if (tid < 4) {
        s_H[tid] = spatial[2 * tid];
        s_W[tid] = spatial[2 * tid + 1];
        s_S[tid] = lstart[tid];
    }
    if (tid < 8) s_ref[tid] = refpts[(size_t)qg * 8 + tid];
    __syncthreads();

    const float* oa = offattn + (size_t)qg * 384;

    // ---- setup: lanes 0-15 handle sample s = lane for this warp's head ----
    if (lane < 16) {
        const int s = lane, l = s >> 2;

        float logit = oa[256 + head * 16 + s];
        float mx = logit;
        #pragma unroll
        for (int d = 8; d; d >>= 1)
            mx = fmaxf(mx, __shfl_xor_sync(0x0000ffffu, mx, d, 16));
        float e = expf(logit - mx);
        float sum = e;
        #pragma unroll
        for (int d = 8; d; d >>= 1)
            sum += __shfl_xor_sync(0x0000ffffu, sum, d, 16);
        const float aw = e / sum;

        const int H = s_H[l], W = s_W[l], st = s_S[l];
        const float Wf = (float)W, Hf = (float)H;
        const float ox = oa[head * 32 + 2 * s];
        const float oy = oa[head * 32 + 2 * s + 1];
        const float lx = s_ref[2 * l]     + ox / Wf;
        const float ly = s_ref[2 * l + 1] + oy / Hf;
        const float x = lx * Wf - 0.5f;
        const float y = ly * Hf - 0.5f;
        const float x0f = floorf(x), y0f = floorf(y);
        const float fx = x - x0f, fy = y - y0f;
        const int x0 = (int)x0f, y0 = (int)y0f;
        const int x1 = x0 + 1, y1 = y0 + 1;

        // pair bases (always a valid in-plane 2x2 block)
        const int p = min(max(x0, 0), W - 2);
        const int q = min(max(y0, 0), H - 2);

        // fold validity+linear weights onto pair pixels (per axis)
        float wp0 = 0.f, wp1 = 0.f;
        if (x0 >= 0 && x0 < W) { if (x0 == p) wp0 += 1.f - fx; else wp1 += 1.f - fx; }
        if (x1 >= 0 && x1 < W) { if (x1 == p) wp0 += fx;       else wp1 += fx; }
        float wq0 = 0.f, wq1 = 0.f;
        if (y0 >= 0 && y0 < H) { if (y0 == q) wq0 += 1.f - fy; else wq1 += 1.f - fy; }
        if (y1 >= 0 && y1 < H) { if (y1 == q) wq0 += fy;       else wq1 += fy; }

        const int base = st + q * W + p;
        float4 r01, r23;
        r01.x = __int_as_float(base * 64);
        r01.y = aw * wq0 * wp0;
        r01.z = __int_as_float((base + 1) * 64);
        r01.w = aw * wq0 * wp1;
        r23.x = __int_as_float((base + W) * 64);
        r23.y = aw * wq1 * wp0;
        r23.z = __int_as_float((base + W + 1) * 64);
        r23.w = aw * wq1 * wp1;
        *(float4*)&s_par[head][s][0] = r01;
        *(float4*)&s_par[head][s][4] = r23;
    }
    __syncwarp();

    // ---- gather: lane = (row, xside, group) ----
    const int g = lane & 7, rxs = lane >> 3;
    const char* vbase =
        (const char*)value + ((size_t)(b * 8 + head) * LEN_IN) * 64 + g * 8;

    float a0 = 0.f, a1 = 0.f, a2 = 0.f, a3 = 0.f;
    #pragma unroll
    for (int s = 0; s < 16; ++s) {
        const float2 rec = *(const float2*)&s_par[head][s][rxs * 2];
        const float w = rec.y;
        const uint2 raw = *(const uint2*)(vbase + __float_as_int(rec.x));
        __half2 h01, h23;
        *(uint32_t*)&h01 = raw.x;
        *(uint32_t*)&h23 = raw.y;
        const float2 f01 = __half22float2(h01);
        const float2 f23 = __half22float2(h23);
        a0 += w * f01.x; a1 += w * f01.y;
        a2 += w * f23.x; a3 += w * f23.y;
    }

    // reduce over xside (xor 8) and row (xor 16)
    #pragma unroll
    for (int d = 8; d <= 16; d <<= 1) {
        a0 += __shfl_xor_sync(0xffffffffu, a0, d);
        a1 += __shfl_xor_sync(0xffffffffu, a1, d);
        a2 += __shfl_xor_sync(0xffffffffu, a2, d);
        a3 += __shfl_xor_sync(0xffffffffu, a3, d);
    }

    if (lane < 8) {
        uint2 o;
        o.x = h2_bits(__floats2half2_rn(a0, a1));
        o.y = h2_bits(__floats2half2_rn(a2, a3));
        *(uint2*)((char*)outcore + (size_t)qg * 512 + head * 64 + g * 8) = o;
    }
}

// ---------------------------------------------------------------------------
extern "C" void kernel_launch(void* const* d_in, const int* in_sizes, int n_in,
                              void* d_out, int out_size)
{
    const float* query   = (const float*)d_in[0];
    const float* refpts  = (const float*)d_in[1];
    const float* input   = (const float*)d_in[2];
    const int*   spatial = (const int*)  d_in[3];
    const int*   lstart  = (const int*)  d_in[4];
    const float* W_off   = (const float*)d_in[5];
    const float* b_off   = (const float*)d_in[6];
    const float* W_attn  = (const float*)d_in[7];
    const float* b_attn  = (const float*)d_in[8];
    const float* W_val   = (const float*)d_in[9];
    const float* b_val   = (const float*)d_in[10];
    const float* W_out   = (const float*)d_in[11];
    const float* b_out   = (const float*)d_in[12];
    float* out = (float*)d_out;

    __half *value, *outcore, *wt;
    float *offattn, *bias_oa;
    cudaGetSymbolAddress((void**)&value,   g_value);
    cudaGetSymbolAddress((void**)&offattn, g_offattn);
    cudaGetSymbolAddress((void**)&outcore, g_outcore);
    cudaGetSymbolAddress((void**)&wt,      g_wt16);
    cudaGetSymbolAddress((void**)&bias_oa, g_bias_oa);
    __half* wt_val     = wt;
    __half* wt_offattn = wt + 65536;
    __half* wt_out     = wt + 65536 + 98304;

    const size_t smem = SMEM_A_BYTES + 2 * B_STAGE;   // 81920 B
    cudaFuncSetAttribute((const void*)gemm_f16<false, 2>,
        cudaFuncAttributeMaxDynamicSharedMemorySize, (int)smem);
    cudaFuncSetAttribute((const void*)gemm_f16<false, 0>,
        cudaFuncAttributeMaxDynamicSharedMemorySize, (int)smem);
    cudaFuncSetAttribute((const void*)gemm_f16<true, 0>,
        cudaFuncAttributeMaxDynamicSharedMemorySize, (int)smem);

    transpose_all<<<dim3(12, 8, 3), dim3(32, 8)>>>(
        W_val, W_off, W_attn, W_out, b_off, b_attn, wt, bias_oa);

    const int MT = NQ / 128;   // 680

    // value projection -> fp16 head-major [B][8][Lin][32]
    gemm_f16<false, 2><<<MT, 256, smem>>>(input, wt_val, b_val, value, 256, 2);
    // fused offsets + attn logits (N=384, 3 tiles, fp32)
    gemm_f16<false, 0><<<MT, 256, smem>>>(query, wt_offattn, bias_oa, offattn, 384, 3);

    msda_sample5<<<NQ, 256>>>(value, offattn, refpts, spatial, lstart, outcore);

    // output projection: A is fp16 outcore -> cp.async path
    gemm_f16<true, 0><<<MT, 256, smem>>>(outcore, wt_out, b_out, out, 256, 2);
}

// round 14
// speedup vs baseline: 1.1784x; 1.1784x over previous
#include <cuda_runtime.h>
#include <cuda_fp16.h>
#include <cstdint>
#include <math.h>

#define B_SZ   4
#define LEN_Q  21760
#define LEN_IN 21760
#define NQ     (B_SZ * LEN_Q)     // 87040
#define DM     256

// Scratch (allocation-free rule: __device__ globals)
__device__ __half g_value[(size_t)NQ * DM];     // [B, Lin, 8, 32] fp16
__device__ float  g_offattn[(size_t)NQ * 384];  // [B*Lq, 256 off | 128 attn]
__device__ __half g_outcore[(size_t)NQ * DM];   // [B*Lq, 256] fp16
__device__ __half g_wt16[256*256 + 384*256 + 256*256]; // wt_val | wt_offattn | wt_out
__device__ float  g_bias_oa[384];               // b_off || b_attn

// ---------------------------------------------------------------------------
// helpers
// ---------------------------------------------------------------------------
__device__ __forceinline__ uint32_t smem_u32(const void* p) {
    uint32_t a;
    asm("{ .reg .u64 t; cvta.to.shared.u64 t, %1; cvt.u32.u64 %0, t; }"
        : "=r"(a) : "l"(p));
    return a;
}
__device__ __forceinline__ uint32_t h2_bits(__half2 h) {
    union { __half2 h; uint32_t u; } cvt;
    cvt.h = h;
    return cvt.u;
}
__device__ __forceinline__ void cp16(uint32_t dst, const void* src) {
    asm volatile("cp.async.ca.shared.global [%0], [%1], 16;"
                 :: "r"(dst), "l"(src) : "memory");
}
#define CP_COMMIT() asm volatile("cp.async.commit_group;" ::: "memory")
#define CP_WAIT(n)  asm volatile("cp.async.wait_group %0;" :: "n"(n) : "memory")

__device__ __forceinline__ void ldm4(uint32_t* r, uint32_t addr) {
    asm volatile("ldmatrix.sync.aligned.m8n8.x4.shared.b16 {%0,%1,%2,%3}, [%4];"
        : "=r"(r[0]), "=r"(r[1]), "=r"(r[2]), "=r"(r[3]) : "r"(addr));
}
__device__ __forceinline__ void mma_f16(float* c, const uint32_t* a, const uint32_t* b) {
    asm volatile(
        "mma.sync.aligned.m16n8k16.row.col.f32.f16.f16.f32 "
        "{%0,%1,%2,%3}, {%4,%5,%6,%7}, {%8,%9}, {%0,%1,%2,%3};"
        : "+f"(c[0]), "+f"(c[1]), "+f"(c[2]), "+f"(c[3])
        : "r"(a[0]), "r"(a[1]), "r"(a[2]), "r"(a[3]), "r"(b[0]), "r"(b[1]));
}
// swizzled offset within a [128 rows x 32 halves] tile
__device__ __forceinline__ uint32_t swz(int row, int kh) {
    return (uint32_t)(row * 64 + ((((kh >> 3) ^ ((row >> 1) & 3))) << 4) + (kh & 7) * 2);
}

// ---------------------------------------------------------------------------
// Fused weight transpose (fp32 -> fp16, [K,N] -> [N,K]) + bias pack.
// ---------------------------------------------------------------------------
__global__ void transpose_all(const float* __restrict__ Wv,
                              const float* __restrict__ Wo,
                              const float* __restrict__ Wa,
                              const float* __restrict__ Wu,
                              const float* __restrict__ b_off,
                              const float* __restrict__ b_attn,
                              __half* __restrict__ wt,
                              float* __restrict__ bias_oa)
{
    const int z = blockIdx.z;
    const int bx = blockIdx.x, by = blockIdx.y;
    const int tx = threadIdx.x, ty = threadIdx.y;
    const int tid = ty * 32 + tx;

    if (z == 1 && bx == 0 && by == 0) {
        if (tid < 256) bias_oa[tid] = b_off[tid];
        if (tid < 128) bias_oa[256 + tid] = b_attn[tid];
    }
    if (z != 1 && bx >= 8) return;
    if (z == 1 && bx >= 12) return;

    const int n0 = bx << 5, k0 = by << 5;
    const float* src;
    __half* dst;
    int N, ncol0;
    if (z == 0)        { src = Wv; dst = wt;                 N = 256; ncol0 = n0; }
    else if (z == 2)   { src = Wu; dst = wt + 65536 + 98304; N = 256; ncol0 = n0; }
    else if (n0 < 256) { src = Wo; dst = wt + 65536;         N = 256; ncol0 = n0; }
    else               { src = Wa; dst = wt + 65536;         N = 128; ncol0 = n0 - 256; }

    __shared__ float t[32][33];
    #pragma unroll
    for (int i = 0; i < 4; ++i)
        t[ty + 8 * i][tx] = src[(size_t)(k0 + ty + 8 * i) * N + ncol0 + tx];
    __syncthreads();
    #pragma unroll
    for (int i = 0; i < 4; ++i)
        dst[(size_t)(n0 + ty + 8 * i) * 256 + k0 + tx] = __float2half(t[tx][ty + 8 * i]);
}

// ---------------------------------------------------------------------------
// A-resident fp16 GEMM body: C[128, ntiles*128] = A[128,256] @ Bt^T + bias
// A tile held in SMEM fp16 (64KB); read from DRAM once per CTA.
// B streamed via 4-stage cp.async ring (4 x 8KB). 8 warps (2M x 4N).
// omode: 0 = fp32 row-major out, 1 = fp16 row-major out.
// ---------------------------------------------------------------------------
#define SMEM_A_BYTES 65536
#define B_STAGE 8192
#define NBSTAGE 4
#define GEMM_SMEM (SMEM_A_BYTES + NBSTAGE * B_STAGE)   // 98304

template<bool A_HALF>
__device__ __forceinline__ void gemm_body(
    const void* __restrict__ Av, const __half* __restrict__ Bt,
    const float* __restrict__ bias, void* __restrict__ Cv,
    int ldc, int ntiles, int omode, char* smc)
{
    const uint32_t sb = smem_u32(smc);          // A region
    const uint32_t sB = sb + SMEM_A_BYTES;      // B ring
    const int tid = threadIdx.x, wid = tid >> 5, lane = tid & 31;
    const int bm = blockIdx.x << 7;
    const int wm = (wid >> 2) << 6;
    const int wn = (wid & 3) << 5;

    const int arow = tid >> 1, ahalf = tid & 1;

    auto cpB = [&](int g) {                     // global chunk g = bn*8 + c
        const int bnp = g >> 3, cp = g & 7;
        const uint32_t dst = sB + (uint32_t)(g & (NBSTAGE - 1)) * B_STAGE;
        #pragma unroll
        for (int j = 0; j < 2; ++j) {
            const int kh = ahalf * 16 + j * 8;
            cp16(dst + swz(arow, kh),
                 Bt + (size_t)(bnp * 128 + arow) * 256 + cp * 32 + kh);
        }
        CP_COMMIT();
    };

    const int G = ntiles * 8;

    if constexpr (A_HALF) {
        const __half* Agh = (const __half*)Av + (size_t)bm * 256;
        #pragma unroll
        for (int c = 0; c < 8; ++c)
            #pragma unroll
            for (int j = 0; j < 2; ++j) {
                const int kh = ahalf * 16 + j * 8;
                cp16(sb + c * B_STAGE + swz(arow, kh),
                     Agh + (size_t)arow * 256 + c * 32 + kh);
            }
        cpB(0);                     // group0 = A(all) + B0
        cpB(1); cpB(2); cpB(3);
    } else {
        cpB(0); cpB(1); cpB(2); cpB(3);
        const float* Ag = (const float*)Av + (size_t)bm * 256;
        #pragma unroll
        for (int c = 0; c < 8; ++c) {
            const float* p = Ag + (size_t)arow * 256 + c * 32 + ahalf * 16;
            #pragma unroll
            for (int j = 0; j < 4; ++j) {
                float4 v = *(const float4*)(p + j * 4);
                const int kh = ahalf * 16 + j * 4;
                uint32_t h01 = h2_bits(__floats2half2_rn(v.x, v.y));
                uint32_t h23 = h2_bits(__floats2half2_rn(v.z, v.w));
                asm volatile("st.shared.v2.b32 [%0], {%1, %2};"
                    :: "r"(sb + c * B_STAGE + swz(arow, kh)), "r"(h01), "r"(h23)
                    : "memory");
            }
        }
    }

    // per-warp ldmatrix lane offsets (within a 32-half chunk; ks=1 -> XOR 32)
    uint32_t aoff[4], boff[2];
    {
        const int ar = (lane & 15), akh = (lane >> 4) * 8;
        #pragma unroll
        for (int mt = 0; mt < 4; ++mt) aoff[mt] = swz(wm + mt * 16 + ar, akh);
        const int br0 = (lane & 7) + ((lane >> 4) << 3), bkh = lane & 8;
        #pragma unroll
        for (int n2 = 0; n2 < 2; ++n2) boff[n2] = swz(wn + n2 * 16 + br0, bkh);
    }
    const int gm = lane >> 2, gn2 = (lane & 3) * 2;

    for (int bn = 0; bn < ntiles; ++bn) {
        float acc[4][4][4] = {};
        #pragma unroll
        for (int c = 0; c < 8; ++c) {
            const int g = bn * 8 + c;
            const uint32_t stA = sb + (uint32_t)c * B_STAGE;
            const uint32_t stB = sB + (uint32_t)(g & (NBSTAGE - 1)) * B_STAGE;
            const int rem = G - 1 - g;          // groups issued after g
            if (rem >= 3)      CP_WAIT(3);
            else if (rem == 2) CP_WAIT(2);
            else if (rem == 1) CP_WAIT(1);
            else               CP_WAIT(0);
            __syncthreads();

            #pragma unroll
            for (int ks = 0; ks < 2; ++ks) {
                const uint32_t xo = ks * 32;
                uint32_t afr[4][4], bfr[2][4];
                #pragma unroll
                for (int mt = 0; mt < 4; ++mt) ldm4(afr[mt], stA + (aoff[mt] ^ xo));
                #pragma unroll
                for (int n2 = 0; n2 < 2; ++n2) ldm4(bfr[n2], stB + (boff[n2] ^ xo));
                #pragma unroll
                for (int mt = 0; mt < 4; ++mt)
                    #pragma unroll
                    for (int nt = 0; nt < 4; ++nt)
                        mma_f16(acc[mt][nt], afr[mt], &bfr[nt >> 1][(nt & 1) * 2]);
            }
            __syncthreads();
            if (g + NBSTAGE < G) cpB(g + NBSTAGE);
        }

        // epilogue for this N-tile
        #pragma unroll
        for (int nt = 0; nt < 4; ++nt) {
            const int col = bn * 128 + wn + nt * 8 + gn2;
            const float b0 = bias[col], b1 = bias[col + 1];
            #pragma unroll
            for (int mt = 0; mt < 4; ++mt) {
                const int r0 = bm + wm + mt * 16 + gm;
                if (omode == 1) {
                    __half* C = (__half*)Cv;
                    *(__half2*)(C + (size_t)r0 * ldc + col) =
                        __floats2half2_rn(acc[mt][nt][0] + b0, acc[mt][nt][1] + b1);
                    *(__half2*)(C + (size_t)(r0 + 8) * ldc + col) =
                        __floats2half2_rn(acc[mt][nt][2] + b0, acc[mt][nt][3] + b1);
                } else {
                    float* C = (float*)Cv;
                    float2 o0 = { acc[mt][nt][0] + b0, acc[mt][nt][1] + b1 };
                    float2 o1 = { acc[mt][nt][2] + b0, acc[mt][nt][3] + b1 };
                    *(float2*)(C + (size_t)r0 * ldc + col) = o0;
                    *(float2*)(C + (size_t)(r0 + 8) * ldc + col) = o1;
                }
            }
        }
    }
}

// Fused value + offattn GEMMs: blockIdx.y selects the problem.
__global__ __launch_bounds__(256, 2)
void gemm_fused(const float* __restrict__ A0, const __half* __restrict__ Bt0,
                const float* __restrict__ bias0, __half* __restrict__ C0,
                const float* __restrict__ A1, const __half* __restrict__ Bt1,
                const float* __restrict__ bias1, float* __restrict__ C1)
{
    extern __shared__ char smc[];
    if (blockIdx.y == 0)
        gemm_body<false>(A0, Bt0, bias0, C0, 256, 2, 1, smc);  // value -> fp16
    else
        gemm_body<false>(A1, Bt1, bias1, C1, 384, 3, 0, smc);  // offattn -> fp32
}

// Output projection: A is fp16 (outcore), C fp32.
__global__ __launch_bounds__(256, 2)
void gemm_out(const __half* __restrict__ A, const __half* __restrict__ Bt,
              const float* __restrict__ bias, float* __restrict__ C)
{
    extern __shared__ char smc[];
    gemm_body<true>(A, Bt, bias, C, 256, 2, 0, smc);
}

// ---------------------------------------------------------------------------
// Deformable sampling v4 (proven): 256 threads = 2 queries x 4 warps.
// Warp w serves heads 2w, 2w+1; lane = (head-half, half2-of-channels).
// Setup parallelizes the 32 (head,sample) parameter sets across lanes;
// gather is 2 LDS.128 + 4 LDG.32(half2) + 8 FFMA per sample. fp16 output.
// ---------------------------------------------------------------------------
__global__ __launch_bounds__(256)
void msda_sample4(const __half* __restrict__ value,   // [B, Lin, 8, 32] fp16
                  const float* __restrict__ offattn,  // [B*Lq, 384]
                  const float* __restrict__ refpts,   // [B, Lq, 4, 2]
                  const int*   __restrict__ spatial,  // [4, 2]
                  const int*   __restrict__ lstart,   // [4]
                  __half* __restrict__ outcore)       // [B*Lq, 256] fp16
{
    const int tid = threadIdx.x;
    const int q   = tid >> 7;                   // query slot 0/1 in block
    const int qg  = blockIdx.x * 2 + q;
    const int b   = qg / LEN_Q;
    const int wid = (tid >> 5) & 3, lane = tid & 31;

    __shared__ float s_ref[2][8];
    __shared__ int   s_H[4], s_W[4], s_S[4];
    __shared__ __align__(16) float s_par[2][8][17][8]; // [q][head][sample][4 idx|4 w]

    if (tid < 4) {
        s_H[tid] = spatial[2 * tid];
        s_W[tid] = spatial[2 * tid + 1];
        s_S[tid] = lstart[tid];
    }
    if ((tid & 127) < 8)
        s_ref[q][tid & 127] = refpts[(size_t)qg * 8 + (tid & 127)];
    __syncthreads();

    const float* oa = offattn + (size_t)qg * 384;

    // ---- setup: one (head, sample) per lane ----
    {
        const int hh = lane >> 4, s = lane & 15;
        const int head = 2 * wid + hh, l = s >> 2;

        float logit = oa[256 + head * 16 + s];
        float mx = logit;
        #pragma unroll
        for (int d = 8; d; d >>= 1) mx = fmaxf(mx, __shfl_xor_sync(0xffffffffu, mx, d, 16));
        float e = expf(logit - mx);
        float sum = e;
        #pragma unroll
        for (int d = 8; d; d >>= 1) sum += __shfl_xor_sync(0xffffffffu, sum, d, 16);
        const float aw = e / sum;

        const int H = s_H[l], W = s_W[l], st = s_S[l];
        const float Wf = (float)W, Hf = (float)H;
        const float ox = oa[head * 32 + 2 * s];
        const float oy = oa[head * 32 + 2 * s + 1];
        const float lx = s_ref[q][2 * l]     + ox / Wf;
        const float ly = s_ref[q][2 * l + 1] + oy / Hf;
        const float x = lx * Wf - 0.5f;
        const float y = ly * Hf - 0.5f;
        const float x0f = floorf(x), y0f = floorf(y);
        const float fx = x - x0f, fy = y - y0f;
        const int x0 = (int)x0f, y0 = (int)y0f;
        const int x1 = x0 + 1, y1 = y0 + 1;

        const float vx0 = (x0 >= 0 && x0 < W) ? 1.f : 0.f;
        const float vx1 = (x1 >= 0 && x1 < W) ? 1.f : 0.f;
        const float vy0 = (y0 >= 0 && y0 < H) ? 1.f : 0.f;
        const float vy1 = (y1 >= 0 && y1 < H) ? 1.f : 0.f;
        const int cx0 = min(max(x0, 0), W - 1), cx1 = min(max(x1, 0), W - 1);
        const int cy0 = min(max(y0, 0), H - 1), cy1 = min(max(y1, 0), H - 1);

        float* p = s_par[q][head][s];
        p[0] = __int_as_float(st + cy0 * W + cx0);
        p[1] = __int_as_float(st + cy0 * W + cx1);
        p[2] = __int_as_float(st + cy1 * W + cx0);
        p[3] = __int_as_float(st + cy1 * W + cx1);
        p[4] = aw * (1.f - fx) * (1.f - fy) * vx0 * vy0;
        p[5] = aw * fx * (1.f - fy) * vx1 * vy0;
        p[6] = aw * (1.f - fx) * fy * vx0 * vy1;
        p[7] = aw * fx * fy * vx1 * vy1;
    }
    __syncwarp();

    // ---- gather ----
    const int hh = lane >> 4, head = 2 * wid + hh, ch2 = lane & 15;
    const __half2* vb =
        (const __half2*)(value + (size_t)b * LEN_IN * 256 + head * 32) + ch2;

    float ax = 0.f, ay = 0.f;
    #pragma unroll
    for (int s = 0; s < 16; ++s) {
        const float4 pi = *(const float4*)&s_par[q][head][s][0];
        const float4 pw = *(const float4*)&s_par[q][head][s][4];
        const float2 v0 = __half22float2(vb[(size_t)__float_as_int(pi.x) * 128]);
        const float2 v1 = __half22float2(vb[(size_t)__float_as_int(pi.y) * 128]);
        const float2 v2 = __half22float2(vb[(size_t)__float_as_int(pi.z) * 128]);
        const float2 v3 = __half22float2(vb[(size_t)__float_as_int(pi.w) * 128]);
        ax += pw.x * v0.x + pw.y * v1.x + pw.z * v2.x + pw.w * v3.x;
        ay += pw.x * v0.y + pw.y * v1.y + pw.z * v2.y + pw.w * v3.y;
    }
    *(__half2*)(outcore + (size_t)qg * 256 + head * 32 + 2 * ch2) =
        __floats2half2_rn(ax, ay);
}

// ---------------------------------------------------------------------------
extern "C" void kernel_launch(void* const* d_in, const int* in_sizes, int n_in,
                              void* d_out, int out_size)
{
    const float* query   = (const float*)d_in[0];
    const float* refpts  = (const float*)d_in[1];
    const float* input   = (const float*)d_in[2];
    const int*   spatial = (const int*)  d_in[3];
    const int*   lstart  = (const int*)  d_in[4];
    const float* W_off   = (const float*)d_in[5];
    const float* b_off   = (const float*)d_in[6];
    const float* W_attn  = (const float*)d_in[7];
    const float* b_attn  = (const float*)d_in[8];
    const float* W_val   = (const float*)d_in[9];
    const float* b_val   = (const float*)d_in[10];
    const float* W_out   = (const float*)d_in[11];
    const float* b_out   = (const float*)d_in[12];
    float* out = (float*)d_out;

    __half *value, *outcore, *wt;
    float *offattn, *bias_oa;
    cudaGetSymbolAddress((void**)&value,   g_value);
    cudaGetSymbolAddress((void**)&offattn, g_offattn);
    cudaGetSymbolAddress((void**)&outcore, g_outcore);
    cudaGetSymbolAddress((void**)&wt,      g_wt16);
    cudaGetSymbolAddress((void**)&bias_oa, g_bias_oa);
    __half* wt_val     = wt;
    __half* wt_offattn = wt + 65536;
    __half* wt_out     = wt + 65536 + 98304;

    cudaFuncSetAttribute((const void*)gemm_fused,
        cudaFuncAttributeMaxDynamicSharedMemorySize, GEMM_SMEM);
    cudaFuncSetAttribute((const void*)gemm_out,
        cudaFuncAttributeMaxDynamicSharedMemorySize, GEMM_SMEM);

    transpose_all<<<dim3(12, 8, 3), dim3(32, 8)>>>(
        W_val, W_off, W_attn, W_out, b_off, b_attn, wt, bias_oa);

    const int MT = NQ / 128;   // 680

    // value projection (-> fp16) + fused offsets/attn logits (-> fp32), one launch
    gemm_fused<<<dim3(MT, 2), 256, GEMM_SMEM>>>(
        input, wt_val, b_val, value,
        query, wt_offattn, bias_oa, offattn);

    msda_sample4<<<NQ / 2, 256>>>(value, offattn, refpts, spatial, lstart, outcore);

    // output projection: A is fp16 outcore -> cp.async path
    gemm_out<<<MT, 256, GEMM_SMEM>>>(outcore, wt_out, b_out, out);
}

// round 15
// speedup vs baseline: 1.2275x; 1.0417x over previous
#include <cuda_runtime.h>
#include <cuda_fp16.h>
#include <cstdint>
#include <math.h>

#define B_SZ   4
#define LEN_Q  21760
#define LEN_IN 21760
#define NQ     (B_SZ * LEN_Q)     // 87040
#define DM     256

// Scratch (allocation-free rule: __device__ globals)
__device__ __half g_value[(size_t)NQ * DM];     // [B, Lin, 8, 32] fp16
__device__ float  g_offattn[(size_t)NQ * 384];  // [B*Lq, 256 off | 128 attn]
__device__ __half g_outcore[(size_t)NQ * DM];   // [B*Lq, 256] fp16
__device__ __half g_wt16[256*256 + 384*256 + 256*256]; // wt_val | wt_offattn | wt_out
__device__ float  g_bias_oa[384];               // b_off || b_attn

// ---------------------------------------------------------------------------
// helpers
// ---------------------------------------------------------------------------
__device__ __forceinline__ uint32_t smem_u32(const void* p) {
    uint32_t a;
    asm("{ .reg .u64 t; cvta.to.shared.u64 t, %1; cvt.u32.u64 %0, t; }"
        : "=r"(a) : "l"(p));
    return a;
}
__device__ __forceinline__ uint32_t h2_bits(__half2 h) {
    union { __half2 h; uint32_t u; } cvt;
    cvt.h = h;
    return cvt.u;
}
__device__ __forceinline__ void cp16(uint32_t dst, const void* src) {
    asm volatile("cp.async.ca.shared.global [%0], [%1], 16;"
                 :: "r"(dst), "l"(src) : "memory");
}
#define CP_COMMIT() asm volatile("cp.async.commit_group;" ::: "memory")
#define CP_WAIT(n)  asm volatile("cp.async.wait_group %0;" :: "n"(n) : "memory")

__device__ __forceinline__ void ldm4(uint32_t* r, uint32_t addr) {
    asm volatile("ldmatrix.sync.aligned.m8n8.x4.shared.b16 {%0,%1,%2,%3}, [%4];"
        : "=r"(r[0]), "=r"(r[1]), "=r"(r[2]), "=r"(r[3]) : "r"(addr));
}
__device__ __forceinline__ void mma_f16(float* c, const uint32_t* a, const uint32_t* b) {
    asm volatile(
        "mma.sync.aligned.m16n8k16.row.col.f32.f16.f16.f32 "
        "{%0,%1,%2,%3}, {%4,%5,%6,%7}, {%8,%9}, {%0,%1,%2,%3};"
        : "+f"(c[0]), "+f"(c[1]), "+f"(c[2]), "+f"(c[3])
        : "r"(a[0]), "r"(a[1]), "r"(a[2]), "r"(a[3]), "r"(b[0]), "r"(b[1]));
}
// swizzled offset within a [128 rows x 32 halves] tile
__device__ __forceinline__ uint32_t swz(int row, int kh) {
    return (uint32_t)(row * 64 + ((((kh >> 3) ^ ((row >> 1) & 3))) << 4) + (kh & 7) * 2);
}

// ---------------------------------------------------------------------------
// Fused weight transpose (fp32 -> fp16, [K,N] -> [N,K]) + bias pack.
// ---------------------------------------------------------------------------
__global__ void transpose_all(const float* __restrict__ Wv,
                              const float* __restrict__ Wo,
                              const float* __restrict__ Wa,
                              const float* __restrict__ Wu,
                              const float* __restrict__ b_off,
                              const float* __restrict__ b_attn,
                              __half* __restrict__ wt,
                              float* __restrict__ bias_oa)
{
    const int z = blockIdx.z;
    const int bx = blockIdx.x, by = blockIdx.y;
    const int tx = threadIdx.x, ty = threadIdx.y;
    const int tid = ty * 32 + tx;

    if (z == 1 && bx == 0 && by == 0) {
        if (tid < 256) bias_oa[tid] = b_off[tid];
        if (tid < 128) bias_oa[256 + tid] = b_attn[tid];
    }
    if (z != 1 && bx >= 8) return;
    if (z == 1 && bx >= 12) return;

    const int n0 = bx << 5, k0 = by << 5;
    const float* src;
    __half* dst;
    int N, ncol0;
    if (z == 0)        { src = Wv; dst = wt;                 N = 256; ncol0 = n0; }
    else if (z == 2)   { src = Wu; dst = wt + 65536 + 98304; N = 256; ncol0 = n0; }
    else if (n0 < 256) { src = Wo; dst = wt + 65536;         N = 256; ncol0 = n0; }
    else               { src = Wa; dst = wt + 65536;         N = 128; ncol0 = n0 - 256; }

    __shared__ float t[32][33];
    #pragma unroll
    for (int i = 0; i < 4; ++i)
        t[ty + 8 * i][tx] = src[(size_t)(k0 + ty + 8 * i) * N + ncol0 + tx];
    __syncthreads();
    #pragma unroll
    for (int i = 0; i < 4; ++i)
        dst[(size_t)(n0 + ty + 8 * i) * 256 + k0 + tx] = __float2half(t[tx][ty + 8 * i]);
}

// ---------------------------------------------------------------------------
// A-resident fp16 GEMM body: C tiles [bn0, bn0+ntiles) of A[128,256] @ Bt^T
// A tile held in SMEM fp16 (64KB); B via 4-stage cp.async ring (4 x 8KB).
// 8 warps (2M x 4N). omode: 0 = fp32 out, 1 = fp16 out.
// ---------------------------------------------------------------------------
#define SMEM_A_BYTES 65536
#define B_STAGE 8192
#define NBSTAGE 4
#define GEMM_SMEM (SMEM_A_BYTES + NBSTAGE * B_STAGE)   // 98304

template<bool A_HALF>
__device__ __forceinline__ void gemm_body(
    const void* __restrict__ Av, const __half* __restrict__ Bt,
    const float* __restrict__ bias, void* __restrict__ Cv,
    int ldc, int bn0, int ntiles, int omode, char* smc)
{
    const uint32_t sb = smem_u32(smc);          // A region
    const uint32_t sB = sb + SMEM_A_BYTES;      // B ring
    const int tid = threadIdx.x, wid = tid >> 5, lane = tid & 31;
    const int bm = blockIdx.x << 7;
    const int wm = (wid >> 2) << 6;
    const int wn = (wid & 3) << 5;

    const int arow = tid >> 1, ahalf = tid & 1;

    auto cpB = [&](int g) {                     // local chunk g = bn*8 + c
        const int bnp = bn0 + (g >> 3), cp = g & 7;
        const uint32_t dst = sB + (uint32_t)(g & (NBSTAGE - 1)) * B_STAGE;
        #pragma unroll
        for (int j = 0; j < 2; ++j) {
            const int kh = ahalf * 16 + j * 8;
            cp16(dst + swz(arow, kh),
                 Bt + (size_t)(bnp * 128 + arow) * 256 + cp * 32 + kh);
        }
        CP_COMMIT();
    };

    const int G = ntiles * 8;

    if constexpr (A_HALF) {
        const __half* Agh = (const __half*)Av + (size_t)bm * 256;
        #pragma unroll
        for (int c = 0; c < 8; ++c)
            #pragma unroll
            for (int j = 0; j < 2; ++j) {
                const int kh = ahalf * 16 + j * 8;
                cp16(sb + c * B_STAGE + swz(arow, kh),
                     Agh + (size_t)arow * 256 + c * 32 + kh);
            }
        cpB(0);                     // group0 = A(all) + B0
        cpB(1); cpB(2); cpB(3);
    } else {
        cpB(0); cpB(1); cpB(2); cpB(3);
        const float* Ag = (const float*)Av + (size_t)bm * 256;
        #pragma unroll
        for (int c = 0; c < 8; ++c) {
            const float* p = Ag + (size_t)arow * 256 + c * 32 + ahalf * 16;
            #pragma unroll
            for (int j = 0; j < 4; ++j) {
                float4 v = *(const float4*)(p + j * 4);
                const int kh = ahalf * 16 + j * 4;
                uint32_t h01 = h2_bits(__floats2half2_rn(v.x, v.y));
                uint32_t h23 = h2_bits(__floats2half2_rn(v.z, v.w));
                asm volatile("st.shared.v2.b32 [%0], {%1, %2};"
                    :: "r"(sb + c * B_STAGE + swz(arow, kh)), "r"(h01), "r"(h23)
                    : "memory");
            }
        }
    }

    // per-warp ldmatrix lane offsets (within a 32-half chunk; ks=1 -> XOR 32)
    uint32_t aoff[4], boff[2];
    {
        const int ar = (lane & 15), akh = (lane >> 4) * 8;
        #pragma unroll
        for (int mt = 0; mt < 4; ++mt) aoff[mt] = swz(wm + mt * 16 + ar, akh);
        const int br0 = (lane & 7) + ((lane >> 4) << 3), bkh = lane & 8;
        #pragma unroll
        for (int n2 = 0; n2 < 2; ++n2) boff[n2] = swz(wn + n2 * 16 + br0, bkh);
    }
    const int gm = lane >> 2, gn2 = (lane & 3) * 2;

    for (int bn = 0; bn < ntiles; ++bn) {
        float acc[4][4][4] = {};
        #pragma unroll
        for (int c = 0; c < 8; ++c) {
            const int g = bn * 8 + c;
            const uint32_t stA = sb + (uint32_t)c * B_STAGE;
            const uint32_t stB = sB + (uint32_t)(g & (NBSTAGE - 1)) * B_STAGE;
            const int rem = G - 1 - g;          // groups issued after g
            if (rem >= 3)      CP_WAIT(3);
            else if (rem == 2) CP_WAIT(2);
            else if (rem == 1) CP_WAIT(1);
            else               CP_WAIT(0);
            __syncthreads();

            #pragma unroll
            for (int ks = 0; ks < 2; ++ks) {
                const uint32_t xo = ks * 32;
                uint32_t afr[4][4], bfr[2][4];
                #pragma unroll
                for (int mt = 0; mt < 4; ++mt) ldm4(afr[mt], stA + (aoff[mt] ^ xo));
                #pragma unroll
                for (int n2 = 0; n2 < 2; ++n2) ldm4(bfr[n2], stB + (boff[n2] ^ xo));
                #pragma unroll
                for (int mt = 0; mt < 4; ++mt)
                    #pragma unroll
                    for (int nt = 0; nt < 4; ++nt)
                        mma_f16(acc[mt][nt], afr[mt], &bfr[nt >> 1][(nt & 1) * 2]);
            }
            __syncthreads();
            if (g + NBSTAGE < G) cpB(g + NBSTAGE);
        }

        // epilogue for this N-tile
        #pragma unroll
        for (int nt = 0; nt < 4; ++nt) {
            const int col = (bn0 + bn) * 128 + wn + nt * 8 + gn2;
            const float b0 = bias[col], b1 = bias[col + 1];
            #pragma unroll
            for (int mt = 0; mt < 4; ++mt) {
                const int r0 = bm + wm + mt * 16 + gm;
                if (omode == 1) {
                    __half* C = (__half*)Cv;
                    *(__half2*)(C + (size_t)r0 * ldc + col) =
                        __floats2half2_rn(acc[mt][nt][0] + b0, acc[mt][nt][1] + b1);
                    *(__half2*)(C + (size_t)(r0 + 8) * ldc + col) =
                        __floats2half2_rn(acc[mt][nt][2] + b0, acc[mt][nt][3] + b1);
                } else {
                    float* C = (float*)Cv;
                    float2 o0 = { acc[mt][nt][0] + b0, acc[mt][nt][1] + b1 };
                    float2 o1 = { acc[mt][nt][2] + b0, acc[mt][nt][3] + b1 };
                    *(float2*)(C + (size_t)r0 * ldc + col) = o0;
                    *(float2*)(C + (size_t)(r0 + 8) * ldc + col) = o1;
                }
            }
        }
    }
}

// Fused value + offattn GEMMs: blockIdx.y selects the problem.
__global__ __launch_bounds__(256, 2)
void gemm_fused(const float* __restrict__ A0, const __half* __restrict__ Bt0,
                const float* __restrict__ bias0, __half* __restrict__ C0,
                const float* __restrict__ A1, const __half* __restrict__ Bt1,
                const float* __restrict__ bias1, float* __restrict__ C1)
{
    extern __shared__ char smc[];
    if (blockIdx.y == 0)
        gemm_body<false>(A0, Bt0, bias0, C0, 256, 0, 2, 1, smc);  // value -> fp16
    else
        gemm_body<false>(A1, Bt1, bias1, C1, 384, 0, 3, 0, smc);  // offattn -> fp32
}

// Output projection: A is fp16 (outcore), C fp32. N-tile = blockIdx.y.
__global__ __launch_bounds__(256, 2)
void gemm_out(const __half* __restrict__ A, const __half* __restrict__ Bt,
              const float* __restrict__ bias, float* __restrict__ C)
{
    extern __shared__ char smc[];
    gemm_body<true>(A, Bt, bias, C, 256, blockIdx.y, 1, 0, smc);
}

// ---------------------------------------------------------------------------
// Deformable sampling v4 (proven): 256 threads = 2 queries x 4 warps.
// Warp w serves heads 2w, 2w+1; lane = (head-half, half2-of-channels).
// __launch_bounds__(256, 7): cap regs at 36 -> 7 blocks/SM (87.5% occ).
// ---------------------------------------------------------------------------
__global__ __launch_bounds__(256, 7)
void msda_sample4(const __half* __restrict__ value,   // [B, Lin, 8, 32] fp16
                  const float* __restrict__ offattn,  // [B*Lq, 384]
                  const float* __restrict__ refpts,   // [B, Lq, 4, 2]
                  const int*   __restrict__ spatial,  // [4, 2]
                  const int*   __restrict__ lstart,   // [4]
                  __half* __restrict__ outcore)       // [B*Lq, 256] fp16
{
    const int tid = threadIdx.x;
    const int q   = tid >> 7;                   // query slot 0/1 in block
    const int qg  = blockIdx.x * 2 + q;
    const int b   = qg / LEN_Q;
    const int wid = (tid >> 5) & 3, lane = tid & 31;

    __shared__ float s_ref[2][8];
    __shared__ int   s_H[4], s_W[4], s_S[4];
    __shared__ __align__(16) float s_par[2][8][17][8]; // [q][head][sample][4 idx|4 w]

    if (tid < 4) {
        s_H[tid] = spatial[2 * tid];
        s_W[tid] = spatial[2 * tid + 1];
        s_S[tid] = lstart[tid];
    }
    if ((tid & 127) < 8)
        s_ref[q][tid & 127] = refpts[(size_t)qg * 8 + (tid & 127)];
    __syncthreads();

    const float* oa = offattn + (size_t)qg * 384;

    // ---- setup: one (head, sample) per lane ----
    {
        const int hh = lane >> 4, s = lane & 15;
        const int head = 2 * wid + hh, l = s >> 2;

        float logit = oa[256 + head * 16 + s];
        float mx = logit;
        #pragma unroll
        for (int d = 8; d; d >>= 1) mx = fmaxf(mx, __shfl_xor_sync(0xffffffffu, mx, d, 16));
        float e = expf(logit - mx);
        float sum = e;
        #pragma unroll
        for (int d = 8; d; d >>= 1) sum += __shfl_xor_sync(0xffffffffu, sum, d, 16);
        const float aw = e / sum;

        const int H = s_H[l], W = s_W[l], st = s_S[l];
        const float Wf = (float)W, Hf = (float)H;
        const float ox = oa[head * 32 + 2 * s];
        const float oy = oa[head * 32 + 2 * s + 1];
        const float lx = s_ref[q][2 * l]     + ox / Wf;
        const float ly = s_ref[q][2 * l + 1] + oy / Hf;
        const float x = lx * Wf - 0.5f;
        const float y = ly * Hf - 0.5f;
        const float x0f = floorf(x), y0f = floorf(y);
        const float fx = x - x0f, fy = y - y0f;
        const int x0 = (int)x0f, y0 = (int)y0f;
        const int x1 = x0 + 1, y1 = y0 + 1;

        const float vx0 = (x0 >= 0 && x0 < W) ? 1.f : 0.f;
        const float vx1 = (x1 >= 0 && x1 < W) ? 1.f : 0.f;
        const float vy0 = (y0 >= 0 && y0 < H) ? 1.f : 0.f;
        const float vy1 = (y1 >= 0 && y1 < H) ? 1.f : 0.f;
        const int cx0 = min(max(x0, 0), W - 1), cx1 = min(max(x1, 0), W - 1);
        const int cy0 = min(max(y0, 0), H - 1), cy1 = min(max(y1, 0), H - 1);

        float* p = s_par[q][head][s];
        p[0] = __int_as_float(st + cy0 * W + cx0);
        p[1] = __int_as_float(st + cy0 * W + cx1);
        p[2] = __int_as_float(st + cy1 * W + cx0);
        p[3] = __int_as_float(st + cy1 * W + cx1);
        p[4] = aw * (1.f - fx) * (1.f - fy) * vx0 * vy0;
        p[5] = aw * fx * (1.f - fy) * vx1 * vy0;
        p[6] = aw * (1.f - fx) * fy * vx0 * vy1;
        p[7] = aw * fx * fy * vx1 * vy1;
    }
    __syncwarp();

    // ---- gather ----
    const int hh = lane >> 4, head = 2 * wid + hh, ch2 = lane & 15;
    const __half2* vb =
        (const __half2*)(value + (size_t)b * LEN_IN * 256 + head * 32) + ch2;

    float ax = 0.f, ay = 0.f;
    #pragma unroll
    for (int s = 0; s < 16; ++s) {
        const float4 pi = *(const float4*)&s_par[q][head][s][0];
        const float4 pw = *(const float4*)&s_par[q][head][s][4];
        const float2 v0 = __half22float2(vb[(size_t)__float_as_int(pi.x) * 128]);
        const float2 v1 = __half22float2(vb[(size_t)__float_as_int(pi.y) * 128]);
        const float2 v2 = __half22float2(vb[(size_t)__float_as_int(pi.z) * 128]);
        const float2 v3 = __half22float2(vb[(size_t)__float_as_int(pi.w) * 128]);
        ax += pw.x * v0.x + pw.y * v1.x + pw.z * v2.x + pw.w * v3.x;
        ay += pw.x * v0.y + pw.y * v1.y + pw.z * v2.y + pw.w * v3.y;
    }
    *(__half2*)(outcore + (size_t)qg * 256 + head * 32 + 2 * ch2) =
        __floats2half2_rn(ax, ay);
}

// ---------------------------------------------------------------------------
extern "C" void kernel_launch(void* const* d_in, const int* in_sizes, int n_in,
                              void* d_out, int out_size)
{
    const float* query   = (const float*)d_in[0];
    const float* refpts  = (const float*)d_in[1];
    const float* input   = (const float*)d_in[2];
    const int*   spatial = (const int*)  d_in[3];
    const int*   lstart  = (const int*)  d_in[4];
    const float* W_off   = (const float*)d_in[5];
    const float* b_off   = (const float*)d_in[6];
    const float* W_attn  = (const float*)d_in[7];
    const float* b_attn  = (const float*)d_in[8];
    const float* W_val   = (const float*)d_in[9];
    const float* b_val   = (const float*)d_in[10];
    const float* W_out   = (const float*)d_in[11];
    const float* b_out   = (const float*)d_in[12];
    float* out = (float*)d_out;

    __half *value, *outcore, *wt;
    float *offattn, *bias_oa;
    cudaGetSymbolAddress((void**)&value,   g_value);
    cudaGetSymbolAddress((void**)&offattn, g_offattn);
    cudaGetSymbolAddress((void**)&outcore, g_outcore);
    cudaGetSymbolAddress((void**)&wt,      g_wt16);
    cudaGetSymbolAddress((void**)&bias_oa, g_bias_oa);
    __half* wt_val     = wt;
    __half* wt_offattn = wt + 65536;
    __half* wt_out     = wt + 65536 + 98304;

    cudaFuncSetAttribute((const void*)gemm_fused,
        cudaFuncAttributeMaxDynamicSharedMemorySize, GEMM_SMEM);
    cudaFuncSetAttribute((const void*)gemm_out,
        cudaFuncAttributeMaxDynamicSharedMemorySize, GEMM_SMEM);

    transpose_all<<<dim3(12, 8, 3), dim3(32, 8)>>>(
        W_val, W_off, W_attn, W_out, b_off, b_attn, wt, bias_oa);

    const int MT = NQ / 128;   // 680

    // value projection (-> fp16) + fused offsets/attn logits (-> fp32), one launch
    gemm_fused<<<dim3(MT, 2), 256, GEMM_SMEM>>>(
        input, wt_val, b_val, value,
        query, wt_offattn, bias_oa, offattn);

    msda_sample4<<<NQ / 2, 256>>>(value, offattn, refpts, spatial, lstart, outcore);

    // output projection: N-tile split across gridDim.y (outcore re-read hits L2)
    gemm_out<<<dim3(MT, 2), 256, GEMM_SMEM>>>(outcore, wt_out, b_out, out);
}

// round 17
// speedup vs baseline: 1.3051x; 1.0631x over previous
#include <cuda_runtime.h>
#include <cuda_fp16.h>
#include <cstdint>
#include <math.h>

#define B_SZ   4
#define LEN_Q  21760
#define LEN_IN 21760
#define NQ     (B_SZ * LEN_Q)     // 87040
#define DM     256

// Scratch (allocation-free rule: __device__ globals)
__device__ __half g_value[(size_t)NQ * DM];     // [B, 8, Lin, 32] fp16 head-major
__device__ float  g_offattn[(size_t)NQ * 384];  // [B*Lq, 256 off | 128 attn] fp32
__device__ __half g_outcore[(size_t)NQ * DM];   // [B*Lq, 256] fp16
__device__ __half g_wt16[256*256 + 384*256 + 256*256]; // wt_val | wt_offattn | wt_out
__device__ float  g_bias_oa[384];               // b_off || b_attn

// ---------------------------------------------------------------------------
// helpers
// ---------------------------------------------------------------------------
__device__ __forceinline__ uint32_t smem_u32(const void* p) {
    uint32_t a;
    asm("{ .reg .u64 t; cvta.to.shared.u64 t, %1; cvt.u32.u64 %0, t; }"
        : "=r"(a) : "l"(p));
    return a;
}
__device__ __forceinline__ uint32_t h2_bits(__half2 h) {
    union { __half2 h; uint32_t u; } cvt;
    cvt.h = h;
    return cvt.u;
}
__device__ __forceinline__ float2 u2f2(uint32_t u) {
    union { uint32_t u; __half2 h; } cvt;
    cvt.u = u;
    return __half22float2(cvt.h);
}
__device__ __forceinline__ void cp16(uint32_t dst, const void* src) {
    asm volatile("cp.async.ca.shared.global [%0], [%1], 16;"
                 :: "r"(dst), "l"(src) : "memory");
}
#define CP_COMMIT() asm volatile("cp.async.commit_group;" ::: "memory")
#define CP_WAIT(n)  asm volatile("cp.async.wait_group %0;" :: "n"(n) : "memory")

__device__ __forceinline__ void ldm4(uint32_t* r, uint32_t addr) {
    asm volatile("ldmatrix.sync.aligned.m8n8.x4.shared.b16 {%0,%1,%2,%3}, [%4];"
        : "=r"(r[0]), "=r"(r[1]), "=r"(r[2]), "=r"(r[3]) : "r"(addr));
}
__device__ __forceinline__ void mma_f16(float* c, const uint32_t* a, const uint32_t* b) {
    asm volatile(
        "mma.sync.aligned.m16n8k16.row.col.f32.f16.f16.f32 "
        "{%0,%1,%2,%3}, {%4,%5,%6,%7}, {%8,%9}, {%0,%1,%2,%3};"
        : "+f"(c[0]), "+f"(c[1]), "+f"(c[2]), "+f"(c[3])
        : "r"(a[0]), "r"(a[1]), "r"(a[2]), "r"(a[3]), "r"(b[0]), "r"(b[1]));
}
// swizzled offset within a [128 rows x 32 halves] tile
__device__ __forceinline__ uint32_t swz(int row, int kh) {
    return (uint32_t)(row * 64 + ((((kh >> 3) ^ ((row >> 1) & 3))) << 4) + (kh & 7) * 2);
}

// ---------------------------------------------------------------------------
// Fused weight transpose (fp32 -> fp16, [K,N] -> [N,K]) + bias pack.
// ---------------------------------------------------------------------------
__global__ void transpose_all(const float* __restrict__ Wv,
                              const float* __restrict__ Wo,
                              const float* __restrict__ Wa,
                              const float* __restrict__ Wu,
                              const float* __restrict__ b_off,
                              const float* __restrict__ b_attn,
                              __half* __restrict__ wt,
                              float* __restrict__ bias_oa)
{
    const int z = blockIdx.z;
    const int bx = blockIdx.x, by = blockIdx.y;
    const int tx = threadIdx.x, ty = threadIdx.y;
    const int tid = ty * 32 + tx;

    if (z == 1 && bx == 0 && by == 0) {
        if (tid < 256) bias_oa[tid] = b_off[tid];
        if (tid < 128) bias_oa[256 + tid] = b_attn[tid];
    }
    if (z != 1 && bx >= 8) return;
    if (z == 1 && bx >= 12) return;

    const int n0 = bx << 5, k0 = by << 5;
    const float* src;
    __half* dst;
    int N, ncol0;
    if (z == 0)        { src = Wv; dst = wt;                 N = 256; ncol0 = n0; }
    else if (z == 2)   { src = Wu; dst = wt + 65536 + 98304; N = 256; ncol0 = n0; }
    else if (n0 < 256) { src = Wo; dst = wt + 65536;         N = 256; ncol0 = n0; }
    else               { src = Wa; dst = wt + 65536;         N = 128; ncol0 = n0 - 256; }

    __shared__ float t[32][33];
    #pragma unroll
    for (int i = 0; i < 4; ++i)
        t[ty + 8 * i][tx] = src[(size_t)(k0 + ty + 8 * i) * N + ncol0 + tx];
    __syncthreads();
    #pragma unroll
    for (int i = 0; i < 4; ++i)
        dst[(size_t)(n0 + ty + 8 * i) * 256 + k0 + tx] = __float2half(t[tx][ty + 8 * i]);
}

// ---------------------------------------------------------------------------
// A-resident fp16 GEMM body: C tiles [bn0, bn0+ntiles) of A[128,256] @ Bt^T
// A tile held in SMEM fp16 (64KB); B via 4-stage cp.async ring (4 x 8KB).
// omode: 0 = fp32 row-major, 1 = fp16 row-major, 2 = fp16 head-major
//        ([B][8][LEN_IN][32]; tiles never cross batches: 21760 = 170*128).
// ---------------------------------------------------------------------------
#define SMEM_A_BYTES 65536
#define B_STAGE 8192
#define NBSTAGE 4
#define GEMM_SMEM (SMEM_A_BYTES + NBSTAGE * B_STAGE)   // 98304

template<bool A_HALF>
__device__ __forceinline__ void gemm_body(
    const void* __restrict__ Av, const __half* __restrict__ Bt,
    const float* __restrict__ bias, void* __restrict__ Cv,
    int ldc, int bn0, int ntiles, int omode, char* smc)
{
    const uint32_t sb = smem_u32(smc);          // A region
    const uint32_t sB = sb + SMEM_A_BYTES;      // B ring
    const int tid = threadIdx.x, wid = tid >> 5, lane = tid & 31;
    const int bm = blockIdx.x << 7;
    const int wm = (wid >> 2) << 6;
    const int wn = (wid & 3) << 5;

    const int arow = tid >> 1, ahalf = tid & 1;

    auto cpB = [&](int g) {                     // local chunk g = bn*8 + c
        const int bnp = bn0 + (g >> 3), cp = g & 7;
        const uint32_t dst = sB + (uint32_t)(g & (NBSTAGE - 1)) * B_STAGE;
        #pragma unroll
        for (int j = 0; j < 2; ++j) {
            const int kh = ahalf * 16 + j * 8;
            cp16(dst + swz(arow, kh),
                 Bt + (size_t)(bnp * 128 + arow) * 256 + cp * 32 + kh);
        }
        CP_COMMIT();
    };

    const int G = ntiles * 8;

    if constexpr (A_HALF) {
        const __half* Agh = (const __half*)Av + (size_t)bm * 256;
        #pragma unroll
        for (int c = 0; c < 8; ++c)
            #pragma unroll
            for (int j = 0; j < 2; ++j) {
                const int kh = ahalf * 16 + j * 8;
                cp16(sb + c * B_STAGE + swz(arow, kh),
                     Agh + (size_t)arow * 256 + c * 32 + kh);
            }
        cpB(0);                     // group0 = A(all) + B0
        cpB(1); cpB(2); cpB(3);
    } else {
        cpB(0); cpB(1); cpB(2); cpB(3);
        const float* Ag = (const float*)Av + (size_t)bm * 256;
        #pragma unroll
        for (int c = 0; c < 8; ++c) {
            const float* p = Ag + (size_t)arow * 256 + c * 32 + ahalf * 16;
            #pragma unroll
            for (int j = 0; j < 4; ++j) {
                float4 v = *(const float4*)(p + j * 4);
                const int kh = ahalf * 16 + j * 4;
                uint32_t h01 = h2_bits(__floats2half2_rn(v.x, v.y));
                uint32_t h23 = h2_bits(__floats2half2_rn(v.z, v.w));
                asm volatile("st.shared.v2.b32 [%0], {%1, %2};"
                    :: "r"(sb + c * B_STAGE + swz(arow, kh)), "r"(h01), "r"(h23)
                    : "memory");
            }
        }
    }

    uint32_t aoff[4], boff[2];
    {
        const int ar = (lane & 15), akh = (lane >> 4) * 8;
        #pragma unroll
        for (int mt = 0; mt < 4; ++mt) aoff[mt] = swz(wm + mt * 16 + ar, akh);
        const int br0 = (lane & 7) + ((lane >> 4) << 3), bkh = lane & 8;
        #pragma unroll
        for (int n2 = 0; n2 < 2; ++n2) boff[n2] = swz(wn + n2 * 16 + br0, bkh);
    }
    const int gm = lane >> 2, gn2 = (lane & 3) * 2;
    const int bq = bm / LEN_IN;                  // batch (omode 2)

    for (int bn = 0; bn < ntiles; ++bn) {
        float acc[4][4][4] = {};
        #pragma unroll
        for (int c = 0; c < 8; ++c) {
            const int g = bn * 8 + c;
            const uint32_t stA = sb + (uint32_t)c * B_STAGE;
            const uint32_t stB = sB + (uint32_t)(g & (NBSTAGE - 1)) * B_STAGE;
            const int rem = G - 1 - g;
            if (rem >= 3)      CP_WAIT(3);
            else if (rem == 2) CP_WAIT(2);
            else if (rem == 1) CP_WAIT(1);
            else               CP_WAIT(0);
            __syncthreads();

            #pragma unroll
            for (int ks = 0; ks < 2; ++ks) {
                const uint32_t xo = ks * 32;
                uint32_t afr[4][4], bfr[2][4];
                #pragma unroll
                for (int mt = 0; mt < 4; ++mt) ldm4(afr[mt], stA + (aoff[mt] ^ xo));
                #pragma unroll
                for (int n2 = 0; n2 < 2; ++n2) ldm4(bfr[n2], stB + (boff[n2] ^ xo));
                #pragma unroll
                for (int mt = 0; mt < 4; ++mt)
                    #pragma unroll
                    for (int nt = 0; nt < 4; ++nt)
                        mma_f16(acc[mt][nt], afr[mt], &bfr[nt >> 1][(nt & 1) * 2]);
            }
            __syncthreads();
            if (g + NBSTAGE < G) cpB(g + NBSTAGE);
        }

        #pragma unroll
        for (int nt = 0; nt < 4; ++nt) {
            const int col = (bn0 + bn) * 128 + wn + nt * 8 + gn2;
            const float b0 = bias[col], b1 = bias[col + 1];
            #pragma unroll
            for (int mt = 0; mt < 4; ++mt) {
                const int r0 = bm + wm + mt * 16 + gm;
                if (omode == 2) {
                    __half* C = (__half*)Cv;
                    const int head = col >> 5, ch = col & 31;
                    const int lr = r0 - bq * LEN_IN;
                    const size_t base =
                        ((size_t)(bq * 8 + head) * LEN_IN + lr) * 32 + ch;
                    *(__half2*)(C + base) =
                        __floats2half2_rn(acc[mt][nt][0] + b0, acc[mt][nt][1] + b1);
                    *(__half2*)(C + base + 8 * 32) =
                        __floats2half2_rn(acc[mt][nt][2] + b0, acc[mt][nt][3] + b1);
                } else if (omode == 1) {
                    __half* C = (__half*)Cv;
                    *(__half2*)(C + (size_t)r0 * ldc + col) =
                        __floats2half2_rn(acc[mt][nt][0] + b0, acc[mt][nt][1] + b1);
                    *(__half2*)(C + (size_t)(r0 + 8) * ldc + col) =
                        __floats2half2_rn(acc[mt][nt][2] + b0, acc[mt][nt][3] + b1);
                } else {
                    float* C = (float*)Cv;
                    float2 o0 = { acc[mt][nt][0] + b0, acc[mt][nt][1] + b1 };
                    float2 o1 = { acc[mt][nt][2] + b0, acc[mt][nt][3] + b1 };
                    *(float2*)(C + (size_t)r0 * ldc + col) = o0;
                    *(float2*)(C + (size_t)(r0 + 8) * ldc + col) = o1;
                }
            }
        }
    }
}

// Fused value + offattn GEMMs: blockIdx.y selects the problem.
__global__ __launch_bounds__(256, 2)
void gemm_fused(const float* __restrict__ A0, const __half* __restrict__ Bt0,
                const float* __restrict__ bias0, __half* __restrict__ C0,
                const float* __restrict__ A1, const __half* __restrict__ Bt1,
                const float* __restrict__ bias1, float* __restrict__ C1)
{
    extern __shared__ char smc[];
    if (blockIdx.y == 0)
        gemm_body<false>(A0, Bt0, bias0, C0, 256, 0, 2, 2, smc);  // value -> fp16 head-major
    else
        gemm_body<false>(A1, Bt1, bias1, C1, 384, 0, 3, 0, smc);  // offattn -> fp32
}

// Output projection: A is fp16 (outcore), C fp32. N-tile = blockIdx.y.
__global__ __launch_bounds__(256, 2)
void gemm_out(const __half* __restrict__ A, const __half* __restrict__ Bt,
              const float* __restrict__ bias, float* __restrict__ C)
{
    extern __shared__ char smc[];
    gemm_body<true>(A, Bt, bias, C, 256, blockIdx.y, 1, 0, smc);
}

// ---------------------------------------------------------------------------
// Deformable sampling v6: 256 threads = 2 queries x 4 warps; warp = 2 heads.
// value is head-major [B][8][Lin][32] so an x-pair is one 128B region.
// Lane = (head-half hh, row r, xside xs, 8-ch group g):
//   one LDG.128 per (warp, sample) covers 2 heads x 2 rows x 128B;
//   one broadcast LDS.128 per lane fetches its row's {pixoff, wx0, wx1}.
// Per-axis clamp/validity fold (verified in R12). End: 16 shfl+add reduce
// over (xs, r); lanes (lane&12)==0 store 8 ch as uint4. fp16 output.
// ---------------------------------------------------------------------------
__global__ __launch_bounds__(256, 5)
void msda_sample6(const __half* __restrict__ value,   // [B, 8, Lin, 32] fp16
                  const float* __restrict__ offattn,  // [B*Lq, 384] fp32
                  const float* __restrict__ refpts,   // [B, Lq, 4, 2]
                  const int*   __restrict__ spatial,  // [4, 2]
                  const int*   __restrict__ lstart,   // [4]
                  __half* __restrict__ outcore)       // [B*Lq, 256] fp16
{
    const int tid = threadIdx.x;
    const int qs  = tid >> 7;                   // query slot 0/1 in block
    const int qg  = blockIdx.x * 2 + qs;
    const int b   = qg / LEN_Q;
    const int wid = (tid >> 5) & 3, lane = tid & 31;

    __shared__ float s_ref[2][8];
    __shared__ int   s_H[4], s_W[4], s_S[4];
    __shared__ __align__(16) float s_par[2][8][16][8]; // [q][head][s][2 x {off,w0,w1,pad}]

    if (tid < 4) {
        s_H[tid] = spatial[2 * tid];
        s_W[tid] = spatial[2 * tid + 1];
        s_S[tid] = lstart[tid];
    }
    if ((tid & 127) < 8)
        s_ref[qs][tid & 127] = refpts[(size_t)qg * 8 + (tid & 127)];
    __syncthreads();

    const float* oa = offattn + (size_t)qg * 384;

    // ---- setup: one (head, sample) per lane ----
    {
        const int hh = lane >> 4, s = lane & 15;
        const int head = 2 * wid + hh, l = s >> 2;

        float logit = oa[256 + head * 16 + s];
        float mx = logit;
        #pragma unroll
        for (int d = 8; d; d >>= 1) mx = fmaxf(mx, __shfl_xor_sync(0xffffffffu, mx, d, 16));
        float e = expf(logit - mx);
        float sum = e;
        #pragma unroll
        for (int d = 8; d; d >>= 1) sum += __shfl_xor_sync(0xffffffffu, sum, d, 16);
        const float aw = e / sum;

        const int H = s_H[l], W = s_W[l], st = s_S[l];
        const float Wf = (float)W, Hf = (float)H;
        const float ox = oa[head * 32 + 2 * s];
        const float oy = oa[head * 32 + 2 * s + 1];
        const float lx = s_ref[qs][2 * l]     + ox / Wf;
        const float ly = s_ref[qs][2 * l + 1] + oy / Hf;
        const float x = lx * Wf - 0.5f;
        const float y = ly * Hf - 0.5f;
        const float x0f = floorf(x), y0f = floorf(y);
        const float fx = x - x0f, fy = y - y0f;
        const int x0 = (int)x0f, y0 = (int)y0f;
        const int x1 = x0 + 1, y1 = y0 + 1;

        const int p  = min(max(x0, 0), W - 2);
        const int qq = min(max(y0, 0), H - 2);

        float wp0 = 0.f, wp1 = 0.f;
        if (x0 >= 0 && x0 < W) { if (x0 == p) wp0 += 1.f - fx; else wp1 += 1.f - fx; }
        if (x1 >= 0 && x1 < W) { if (x1 == p) wp0 += fx;       else wp1 += fx; }
        float wq0 = 0.f, wq1 = 0.f;
        if (y0 >= 0 && y0 < H) { if (y0 == qq) wq0 += 1.f - fy; else wq1 += 1.f - fy; }
        if (y1 >= 0 && y1 < H) { if (y1 == qq) wq0 += fy;       else wq1 += fy; }

        const int base = st + qq * W + p;
        float4 r0, r1;
        r0.x = __int_as_float(base * 64);          // row0 x-pair byte offset
        r0.y = aw * wq0 * wp0;
        r0.z = aw * wq0 * wp1;
        r0.w = 0.f;
        r1.x = __int_as_float((base + W) * 64);    // row1
        r1.y = aw * wq1 * wp0;
        r1.z = aw * wq1 * wp1;
        r1.w = 0.f;
        *(float4*)&s_par[qs][head][s][0] = r0;
        *(float4*)&s_par[qs][head][s][4] = r1;
    }
    __syncwarp();

    // ---- gather: lane = (hh, r, xs, g) ----
    const int hh = lane >> 4, head = 2 * wid + hh;
    const int r = (lane >> 3) & 1, xs = (lane >> 2) & 1, g = lane & 3;
    const char* vb = (const char*)value
        + ((size_t)(b * 8 + head) * LEN_IN) * 64 + xs * 64 + g * 16;
    const float* ph = &s_par[qs][head][0][r * 4];

    float a0 = 0.f, a1 = 0.f, a2 = 0.f, a3 = 0.f;
    float a4 = 0.f, a5 = 0.f, a6 = 0.f, a7 = 0.f;
    #pragma unroll
    for (int s = 0; s < 16; ++s) {
        const float4 rec = *(const float4*)(ph + s * 8);
        const float w = xs ? rec.z : rec.y;
        const uint4 raw = *(const uint4*)(vb + __float_as_int(rec.x));
        const float2 f0 = u2f2(raw.x);
        const float2 f1 = u2f2(raw.y);
        const float2 f2 = u2f2(raw.z);
        const float2 f3 = u2f2(raw.w);
        a0 += w * f0.x; a1 += w * f0.y;
        a2 += w * f1.x; a3 += w * f1.y;
        a4 += w * f2.x; a5 += w * f2.y;
        a6 += w * f3.x; a7 += w * f3.y;
    }

    // reduce over xside (xor 4) and row (xor 8)
    #pragma unroll
    for (int d = 4; d <= 8; d <<= 1) {
        a0 += __shfl_xor_sync(0xffffffffu, a0, d);
        a1 += __shfl_xor_sync(0xffffffffu, a1, d);
        a2 += __shfl_xor_sync(0xffffffffu, a2, d);
        a3 += __shfl_xor_sync(0xffffffffu, a3, d);
        a4 += __shfl_xor_sync(0xffffffffu, a4, d);
        a5 += __shfl_xor_sync(0xffffffffu, a5, d);
        a6 += __shfl_xor_sync(0xffffffffu, a6, d);
        a7 += __shfl_xor_sync(0xffffffffu, a7, d);
    }

    if ((lane & 12) == 0) {
        uint4 o;
        o.x = h2_bits(__floats2half2_rn(a0, a1));
        o.y = h2_bits(__floats2half2_rn(a2, a3));
        o.z = h2_bits(__floats2half2_rn(a4, a5));
        o.w = h2_bits(__floats2half2_rn(a6, a7));
        *(uint4*)((char*)outcore + (size_t)qg * 512 + head * 64 + g * 16) = o;
    }
}

// ---------------------------------------------------------------------------
extern "C" void kernel_launch(void* const* d_in, const int* in_sizes, int n_in,
                              void* d_out, int out_size)
{
    const float* query   = (const float*)d_in[0];
    const float* refpts  = (const float*)d_in[1];
    const float* input   = (const float*)d_in[2];
    const int*   spatial = (const int*)  d_in[3];
    const int*   lstart  = (const int*)  d_in[4];
    const float* W_off   = (const float*)d_in[5];
    const float* b_off   = (const float*)d_in[6];
    const float* W_attn  = (const float*)d_in[7];
    const float* b_attn  = (const float*)d_in[8];
    const float* W_val   = (const float*)d_in[9];
    const float* b_val   = (const float*)d_in[10];
    const float* W_out   = (const float*)d_in[11];
    const float* b_out   = (const float*)d_in[12];
    float* out = (float*)d_out;

    __half *value, *outcore, *wt;
    float *offattn, *bias_oa;
    cudaGetSymbolAddress((void**)&value,   g_value);
    cudaGetSymbolAddress((void**)&offattn, g_offattn);
    cudaGetSymbolAddress((void**)&outcore, g_outcore);
    cudaGetSymbolAddress((void**)&wt,      g_wt16);
    cudaGetSymbolAddress((void**)&bias_oa, g_bias_oa);
    __half* wt_val     = wt;
    __half* wt_offattn = wt + 65536;
    __half* wt_out     = wt + 65536 + 98304;

    cudaFuncSetAttribute((const void*)gemm_fused,
        cudaFuncAttributeMaxDynamicSharedMemorySize, GEMM_SMEM);
    cudaFuncSetAttribute((const void*)gemm_out,
        cudaFuncAttributeMaxDynamicSharedMemorySize, GEMM_SMEM);

    transpose_all<<<dim3(12, 8, 3), dim3(32, 8)>>>(
        W_val, W_off, W_attn, W_out, b_off, b_attn, wt, bias_oa);

    const int MT = NQ / 128;   // 680

    // value projection (-> fp16 head-major) + offsets/attn logits (-> fp32)
    gemm_fused<<<dim3(MT, 2), 256, GEMM_SMEM>>>(
        input, wt_val, b_val, value,
        query, wt_offattn, bias_oa, offattn);

    msda_sample6<<<NQ / 2, 256>>>(value, offattn, refpts, spatial, lstart, outcore);

    // output projection: N-tile split across gridDim.y (outcore re-read hits L2)
    gemm_out<<<dim3(MT, 2), 256, GEMM_SMEM>>>(outcore, wt_out, b_out, out);
}